// round 1
// baseline (speedup 1.0000x reference)
#include <cuda_runtime.h>

#define N_NODES 100000
#define F_IN  128
#define F_MID 64
#define F_OUT 32

// ---------------- scratch (device globals; no allocations allowed) ----------
__device__ float g_deg_out[N_NODES];           // becomes out_norm in place
__device__ float g_deg_in [N_NODES];           // becomes in_norm  in place
__device__ float g_h1  [N_NODES * F_MID];      // (x*out_norm)@W1
__device__ float g_agg1[N_NODES * F_MID];      // scatter target layer 1
__device__ float g_h2  [N_NODES * F_OUT];      // (x1*out_norm)@W2

// ---------------- zero scratch + output -------------------------------------
__global__ void zero_kernel(float* __restrict__ out) {
    int i = blockIdx.x * 256 + threadIdx.x;
    if (i < N_NODES * F_MID) g_agg1[i] = 0.f;
    if (i < N_NODES * F_OUT) out[i]    = 0.f;
    if (i < N_NODES) { g_deg_out[i] = 0.f; g_deg_in[i] = 0.f; }
}

// ---------------- degrees ----------------------------------------------------
__global__ void degree_kernel(const int* __restrict__ src,
                              const int* __restrict__ dst, int E) {
    int e = blockIdx.x * 256 + threadIdx.x;
    if (e < E) {
        atomicAdd(&g_deg_out[src[e]], 1.0f);
        atomicAdd(&g_deg_in [dst[e]], 1.0f);
    }
}

__global__ void norm_kernel() {
    int i = blockIdx.x * 256 + threadIdx.x;
    if (i < N_NODES) {
        g_deg_out[i] = rsqrtf(fmaxf(g_deg_out[i], 1.0f));
        g_deg_in [i] = rsqrtf(fmaxf(g_deg_in [i], 1.0f));
    }
}

// ---------------- GEMM1: h1 = (x * out_norm) @ W1  [N,128]@[128,64] ----------
// 256 threads, tile 64 rows x 64 cols, K tiled by 16, 4x4 per-thread tile.
__global__ void gemm1_kernel(const float* __restrict__ x,
                             const float* __restrict__ W) {
    __shared__ float xs[64][20];   // padded (bank-spread for stores)
    __shared__ float ws[16][64];

    int tid = threadIdx.x;
    int tx  = tid & 15;            // col group (cols tx*4 .. tx*4+3)
    int ty  = tid >> 4;            // row group (rows ty*4 .. ty*4+3)
    int row0 = blockIdx.x * 64;

    // load mapping for xs: each thread loads one float4 of one row
    int lr  = tid >> 2;            // 0..63
    int lk4 = tid & 3;             // 0..3  (k offset lk4*4 within 16)
    int grow = min(row0 + lr, N_NODES - 1);
    float nrm = g_deg_out[grow];

    float acc[4][4] = {};

    for (int k0 = 0; k0 < F_IN; k0 += 16) {
        float4 xv = *(const float4*)&x[(long long)grow * F_IN + k0 + lk4 * 4];
        xs[lr][lk4 * 4 + 0] = xv.x * nrm;
        xs[lr][lk4 * 4 + 1] = xv.y * nrm;
        xs[lr][lk4 * 4 + 2] = xv.z * nrm;
        xs[lr][lk4 * 4 + 3] = xv.w * nrm;
        // W tile: row k0+ty (0..15), col tx*4
        float4 wv = *(const float4*)&W[(k0 + ty) * F_MID + tx * 4];
        *(float4*)&ws[ty][tx * 4] = wv;
        __syncthreads();

        #pragma unroll
        for (int k = 0; k < 16; k++) {
            float a0 = xs[ty * 4 + 0][k];
            float a1 = xs[ty * 4 + 1][k];
            float a2 = xs[ty * 4 + 2][k];
            float a3 = xs[ty * 4 + 3][k];
            float4 b = *(const float4*)&ws[k][tx * 4];
            acc[0][0] += a0 * b.x; acc[0][1] += a0 * b.y; acc[0][2] += a0 * b.z; acc[0][3] += a0 * b.w;
            acc[1][0] += a1 * b.x; acc[1][1] += a1 * b.y; acc[1][2] += a1 * b.z; acc[1][3] += a1 * b.w;
            acc[2][0] += a2 * b.x; acc[2][1] += a2 * b.y; acc[2][2] += a2 * b.z; acc[2][3] += a2 * b.w;
            acc[3][0] += a3 * b.x; acc[3][1] += a3 * b.y; acc[3][2] += a3 * b.z; acc[3][3] += a3 * b.w;
        }
        __syncthreads();
    }

    #pragma unroll
    for (int i = 0; i < 4; i++) {
        int r = row0 + ty * 4 + i;
        if (r < N_NODES)
            *(float4*)&g_h1[(long long)r * F_MID + tx * 4] =
                make_float4(acc[i][0], acc[i][1], acc[i][2], acc[i][3]);
    }
}

// ---------------- edge scatter layer 1: agg1[dst] += h1[src] ----------------
// one thread per (edge, float4-chunk); 16 chunks per edge.
__global__ void edge1_kernel(const int* __restrict__ src,
                             const int* __restrict__ dst, int E) {
    long long t = (long long)blockIdx.x * 256 + threadIdx.x;
    int e = (int)(t >> 4);
    int c = (int)(t & 15);
    if (e < E) {
        int s = __ldg(&src[e]);
        int d = __ldg(&dst[e]);
        float4 v = *(const float4*)&g_h1[(long long)s * F_MID + c * 4];
        float* p = &g_agg1[(long long)d * F_MID + c * 4];
        asm volatile("red.global.add.v4.f32 [%0], {%1,%2,%3,%4};"
                     :: "l"(p), "f"(v.x), "f"(v.y), "f"(v.z), "f"(v.w)
                     : "memory");
    }
}

// ---------------- GEMM2: h2 = (relu(agg1*in_norm+b1) * out_norm) @ W2 -------
// [N,64]@[64,32]; 256 threads, tile 128 rows x 32 cols, K tiled by 16.
__global__ void gemm2_kernel(const float* __restrict__ W,
                             const float* __restrict__ b1) {
    __shared__ float xs[128][20];
    __shared__ float ws[16][32];

    int tid = threadIdx.x;
    int tx  = tid & 7;             // col group (cols tx*4)
    int ty  = tid >> 3;            // row group (rows ty*4), 0..31
    int row0 = blockIdx.x * 128;

    int lr  = tid >> 1;            // 0..127
    int lk8 = tid & 1;             // loads 8 floats at k offset lk8*8
    int grow = min(row0 + lr, N_NODES - 1);
    float sc_in  = g_deg_in[grow];
    float sc_out = g_deg_out[grow];

    float acc[4][4] = {};

    for (int k0 = 0; k0 < F_MID; k0 += 16) {
        #pragma unroll
        for (int h = 0; h < 2; h++) {
            int kk = k0 + lk8 * 8 + h * 4;
            float4 av = *(const float4*)&g_agg1[(long long)grow * F_MID + kk];
            float4 bv = *(const float4*)&b1[kk];
            xs[lr][lk8 * 8 + h * 4 + 0] = fmaxf(fmaf(av.x, sc_in, bv.x), 0.f) * sc_out;
            xs[lr][lk8 * 8 + h * 4 + 1] = fmaxf(fmaf(av.y, sc_in, bv.y), 0.f) * sc_out;
            xs[lr][lk8 * 8 + h * 4 + 2] = fmaxf(fmaf(av.z, sc_in, bv.z), 0.f) * sc_out;
            xs[lr][lk8 * 8 + h * 4 + 3] = fmaxf(fmaf(av.w, sc_in, bv.w), 0.f) * sc_out;
        }
        // W tile: 16x32 = 512 floats, 2 per thread
        {
            int wk  = tid >> 4;    // 0..15
            int wc2 = tid & 15;    // 0..15 -> 2 floats
            ws[wk][wc2 * 2 + 0] = W[(k0 + wk) * F_OUT + wc2 * 2 + 0];
            ws[wk][wc2 * 2 + 1] = W[(k0 + wk) * F_OUT + wc2 * 2 + 1];
        }
        __syncthreads();

        #pragma unroll
        for (int k = 0; k < 16; k++) {
            float a0 = xs[ty * 4 + 0][k];
            float a1 = xs[ty * 4 + 1][k];
            float a2 = xs[ty * 4 + 2][k];
            float a3 = xs[ty * 4 + 3][k];
            float4 b = *(const float4*)&ws[k][tx * 4];
            acc[0][0] += a0 * b.x; acc[0][1] += a0 * b.y; acc[0][2] += a0 * b.z; acc[0][3] += a0 * b.w;
            acc[1][0] += a1 * b.x; acc[1][1] += a1 * b.y; acc[1][2] += a1 * b.z; acc[1][3] += a1 * b.w;
            acc[2][0] += a2 * b.x; acc[2][1] += a2 * b.y; acc[2][2] += a2 * b.z; acc[2][3] += a2 * b.w;
            acc[3][0] += a3 * b.x; acc[3][1] += a3 * b.y; acc[3][2] += a3 * b.z; acc[3][3] += a3 * b.w;
        }
        __syncthreads();
    }

    #pragma unroll
    for (int i = 0; i < 4; i++) {
        int r = row0 + ty * 4 + i;
        if (r < N_NODES)
            *(float4*)&g_h2[(long long)r * F_OUT + tx * 4] =
                make_float4(acc[i][0], acc[i][1], acc[i][2], acc[i][3]);
    }
}

// ---------------- edge scatter layer 2: out[dst] += h2[src] -----------------
__global__ void edge2_kernel(const int* __restrict__ src,
                             const int* __restrict__ dst, int E,
                             float* __restrict__ out) {
    long long t = (long long)blockIdx.x * 256 + threadIdx.x;
    int e = (int)(t >> 3);
    int c = (int)(t & 7);
    if (e < E) {
        int s = __ldg(&src[e]);
        int d = __ldg(&dst[e]);
        float4 v = *(const float4*)&g_h2[(long long)s * F_OUT + c * 4];
        float* p = &out[(long long)d * F_OUT + c * 4];
        asm volatile("red.global.add.v4.f32 [%0], {%1,%2,%3,%4};"
                     :: "l"(p), "f"(v.x), "f"(v.y), "f"(v.z), "f"(v.w)
                     : "memory");
    }
}

// ---------------- epilogue: out = out*in_norm + b2 --------------------------
__global__ void epi_kernel(float* __restrict__ out, const float* __restrict__ b2) {
    int i4 = blockIdx.x * 256 + threadIdx.x;   // over N*8 float4
    if (i4 < N_NODES * (F_OUT / 4)) {
        int node = i4 >> 3;
        int c4   = i4 & 7;
        float sc = g_deg_in[node];
        float4 v = ((float4*)out)[i4];
        float4 b = *(const float4*)&b2[c4 * 4];
        v.x = fmaf(v.x, sc, b.x);
        v.y = fmaf(v.y, sc, b.y);
        v.z = fmaf(v.z, sc, b.z);
        v.w = fmaf(v.w, sc, b.w);
        ((float4*)out)[i4] = v;
    }
}

// ---------------- launch -----------------------------------------------------
extern "C" void kernel_launch(void* const* d_in, const int* in_sizes, int n_in,
                              void* d_out, int out_size) {
    const float* x   = (const float*)d_in[0];
    const int*   src = (const int*)  d_in[1];   // JAX default: int64 request -> int32
    const int*   dst = (const int*)  d_in[2];
    const float* W1  = (const float*)d_in[3];
    const float* b1  = (const float*)d_in[4];
    const float* W2  = (const float*)d_in[5];
    const float* b2  = (const float*)d_in[6];
    int E = in_sizes[1];
    float* out = (float*)d_out;

    zero_kernel  <<<(N_NODES * F_MID + 255) / 256, 256>>>(out);
    degree_kernel<<<(E + 255) / 256, 256>>>(src, dst, E);
    norm_kernel  <<<(N_NODES + 255) / 256, 256>>>();
    gemm1_kernel <<<(N_NODES + 63) / 64, 256>>>(x, W1);
    edge1_kernel <<<(unsigned)(((long long)E * 16 + 255) / 256), 256>>>(src, dst, E);
    gemm2_kernel <<<(N_NODES + 127) / 128, 256>>>(W2, b1);
    edge2_kernel <<<(unsigned)(((long long)E * 8 + 255) / 256), 256>>>(src, dst, E, out);
    epi_kernel   <<<(N_NODES * (F_OUT / 4) + 255) / 256, 256>>>(out, b2);
}

// round 2
// speedup vs baseline: 1.3768x; 1.3768x over previous
#include <cuda_runtime.h>

#define N_NODES 100000
#define E_MAX   1600000
#define F_IN  128
#define F_MID 64
#define F_OUT 32

// ---------------- scratch (device globals; no allocations allowed) ----------
__device__ int   g_out_deg[N_NODES];
__device__ int   g_in_deg [N_NODES];
__device__ int   g_cnt    [N_NODES];
__device__ float g_nrm_out[N_NODES];
__device__ float g_nrm_in [N_NODES];
__device__ int   g_row_ptr[N_NODES];
__device__ int   g_blk_sum[512];
__device__ int   g_blk_off[512];
__device__ int   g_csr_src[E_MAX];
__device__ float g_h1[N_NODES * F_MID];   // out_norm*(x@W1)
__device__ float g_xr[N_NODES * F_MID];   // relu(agg*in_norm+b1)*out_norm
__device__ float g_h2[N_NODES * F_OUT];   // xr@W2

// ---------------- zero the int counters ------------------------------------
__global__ void zero_kernel() {
    int i = blockIdx.x * 256 + threadIdx.x;
    if (i < N_NODES) { g_out_deg[i] = 0; g_in_deg[i] = 0; g_cnt[i] = 0; }
}

// ---------------- degrees (int atomics) -------------------------------------
__global__ void degree_kernel(const int* __restrict__ src,
                              const int* __restrict__ dst, int E) {
    int e = blockIdx.x * 256 + threadIdx.x;
    if (e < E) {
        atomicAdd(&g_out_deg[src[e]], 1);
        atomicAdd(&g_in_deg [dst[e]], 1);
    }
}

__global__ void norm_kernel() {
    int i = blockIdx.x * 256 + threadIdx.x;
    if (i < N_NODES) {
        g_nrm_out[i] = rsqrtf((float)max(g_out_deg[i], 1));
        g_nrm_in [i] = rsqrtf((float)max(g_in_deg [i], 1));
    }
}

// ---------------- 3-phase exclusive scan of in_deg -> row_ptr ---------------
__global__ void scan1_kernel() {
    int tid = threadIdx.x;
    int i = blockIdx.x * 512 + tid;
    int v = (i < N_NODES) ? g_in_deg[i] : 0;
    int lane = tid & 31, w = tid >> 5;
    int x = v;
    #pragma unroll
    for (int o = 1; o < 32; o <<= 1) {
        int t = __shfl_up_sync(0xffffffffu, x, o);
        if (lane >= o) x += t;
    }
    __shared__ int wsum[16];
    if (lane == 31) wsum[w] = x;
    __syncthreads();
    if (w == 0) {
        int t = (lane < 16) ? wsum[lane] : 0;
        #pragma unroll
        for (int o = 1; o < 16; o <<= 1) {
            int u = __shfl_up_sync(0xffffffffu, t, o);
            if (lane >= o) t += u;
        }
        if (lane < 16) wsum[lane] = t;
    }
    __syncthreads();
    int base = (w > 0) ? wsum[w - 1] : 0;
    if (i < N_NODES) g_row_ptr[i] = base + x - v;
    if (tid == 511) g_blk_sum[blockIdx.x] = wsum[15];
}

__global__ void scan2_kernel(int nblk) {
    int tid = threadIdx.x;           // 256 threads
    int v = (tid < nblk) ? g_blk_sum[tid] : 0;
    int lane = tid & 31, w = tid >> 5;
    int x = v;
    #pragma unroll
    for (int o = 1; o < 32; o <<= 1) {
        int t = __shfl_up_sync(0xffffffffu, x, o);
        if (lane >= o) x += t;
    }
    __shared__ int wsum[8];
    if (lane == 31) wsum[w] = x;
    __syncthreads();
    if (w == 0) {
        int t = (lane < 8) ? wsum[lane] : 0;
        #pragma unroll
        for (int o = 1; o < 8; o <<= 1) {
            int u = __shfl_up_sync(0xffffffffu, t, o);
            if (lane >= o) t += u;
        }
        if (lane < 8) wsum[lane] = t;
    }
    __syncthreads();
    int base = (w > 0) ? wsum[w - 1] : 0;
    if (tid < nblk) g_blk_off[tid] = base + x - v;
}

__global__ void scan3_kernel() {
    int i = blockIdx.x * 512 + threadIdx.x;
    if (i < N_NODES) g_row_ptr[i] += g_blk_off[blockIdx.x];
}

// ---------------- CSR fill ---------------------------------------------------
__global__ void fill_kernel(const int* __restrict__ src,
                            const int* __restrict__ dst, int E) {
    int e = blockIdx.x * 256 + threadIdx.x;
    if (e < E) {
        int d = dst[e];
        int pos = g_row_ptr[d] + atomicAdd(&g_cnt[d], 1);
        g_csr_src[pos] = src[e];
    }
}

// ---------------- GEMM1: h1 = out_norm * (x @ W1)  [N,128]@[128,64] ----------
// 128 threads, tile 128 rows x 64 cols, 8x8 per-thread register tile.
__global__ void gemm1_kernel(const float* __restrict__ x,
                             const float* __restrict__ W) {
    __shared__ float xs[128][17];
    __shared__ float ws[16][68];

    int tid = threadIdx.x;
    int tx  = tid & 7;              // col group: cols tx*8..+7
    int ty  = tid >> 3;             // row group: rows ty*8..+7
    int row0 = blockIdx.x * 128;

    float acc[8][8] = {};

    for (int k0 = 0; k0 < F_IN; k0 += 16) {
        // x tile 128x16, coalesced-ish float4 loads, scalar STS
        #pragma unroll
        for (int p = 0; p < 4; p++) {
            int f  = p * 128 + tid;
            int r  = f >> 2;
            int kq = f & 3;
            int gr = min(row0 + r, N_NODES - 1);
            float4 v = *(const float4*)&x[(size_t)gr * F_IN + k0 + kq * 4];
            xs[r][kq * 4 + 0] = v.x;
            xs[r][kq * 4 + 1] = v.y;
            xs[r][kq * 4 + 2] = v.z;
            xs[r][kq * 4 + 3] = v.w;
        }
        // W tile 16x64
        {
            int wk = tid >> 3, wc = tid & 7;
            *(float4*)&ws[wk][wc * 8]     = *(const float4*)&W[(k0 + wk) * F_MID + wc * 8];
            *(float4*)&ws[wk][wc * 8 + 4] = *(const float4*)&W[(k0 + wk) * F_MID + wc * 8 + 4];
        }
        __syncthreads();

        #pragma unroll
        for (int k = 0; k < 16; k++) {
            float a[8], b[8];
            #pragma unroll
            for (int i = 0; i < 8; i++) a[i] = xs[ty * 8 + i][k];
            *(float4*)&b[0] = *(float4*)&ws[k][tx * 8];
            *(float4*)&b[4] = *(float4*)&ws[k][tx * 8 + 4];
            #pragma unroll
            for (int i = 0; i < 8; i++)
                #pragma unroll
                for (int j = 0; j < 8; j++)
                    acc[i][j] += a[i] * b[j];
        }
        __syncthreads();
    }

    #pragma unroll
    for (int i = 0; i < 8; i++) {
        int r = row0 + ty * 8 + i;
        if (r < N_NODES) {
            float nm = g_nrm_out[r];
            float4 o0 = make_float4(acc[i][0]*nm, acc[i][1]*nm, acc[i][2]*nm, acc[i][3]*nm);
            float4 o1 = make_float4(acc[i][4]*nm, acc[i][5]*nm, acc[i][6]*nm, acc[i][7]*nm);
            *(float4*)&g_h1[(size_t)r * F_MID + tx * 8]     = o0;
            *(float4*)&g_h1[(size_t)r * F_MID + tx * 8 + 4] = o1;
        }
    }
}

// ---------------- pull layer 1: xr = relu(sum(h1[src])*in_norm + b1)*out_norm
// 16 threads per node (one float4 chunk each), 16 nodes per 256-thread block.
__global__ void pull1_kernel(const float* __restrict__ b1) {
    int t = threadIdx.x;
    int node = blockIdx.x * 16 + (t >> 4);
    int c = t & 15;
    if (node >= N_NODES) return;
    int beg = g_row_ptr[node];
    int deg = g_in_deg[node];
    float4 acc = make_float4(0.f, 0.f, 0.f, 0.f);
    int j = 0;
    for (; j + 4 <= deg; j += 4) {
        int s0 = __ldg(&g_csr_src[beg + j + 0]);
        int s1 = __ldg(&g_csr_src[beg + j + 1]);
        int s2 = __ldg(&g_csr_src[beg + j + 2]);
        int s3 = __ldg(&g_csr_src[beg + j + 3]);
        float4 v0 = *(const float4*)&g_h1[(size_t)s0 * F_MID + c * 4];
        float4 v1 = *(const float4*)&g_h1[(size_t)s1 * F_MID + c * 4];
        float4 v2 = *(const float4*)&g_h1[(size_t)s2 * F_MID + c * 4];
        float4 v3 = *(const float4*)&g_h1[(size_t)s3 * F_MID + c * 4];
        acc.x += (v0.x + v1.x) + (v2.x + v3.x);
        acc.y += (v0.y + v1.y) + (v2.y + v3.y);
        acc.z += (v0.z + v1.z) + (v2.z + v3.z);
        acc.w += (v0.w + v1.w) + (v2.w + v3.w);
    }
    for (; j < deg; j++) {
        int s = __ldg(&g_csr_src[beg + j]);
        float4 v = *(const float4*)&g_h1[(size_t)s * F_MID + c * 4];
        acc.x += v.x; acc.y += v.y; acc.z += v.z; acc.w += v.w;
    }
    float ni = g_nrm_in[node];
    float no = g_nrm_out[node];
    float4 bb = *(const float4*)&b1[c * 4];
    float4 r;
    r.x = fmaxf(fmaf(acc.x, ni, bb.x), 0.f) * no;
    r.y = fmaxf(fmaf(acc.y, ni, bb.y), 0.f) * no;
    r.z = fmaxf(fmaf(acc.z, ni, bb.z), 0.f) * no;
    r.w = fmaxf(fmaf(acc.w, ni, bb.w), 0.f) * no;
    *(float4*)&g_xr[(size_t)node * F_MID + c * 4] = r;
}

// ---------------- GEMM2: h2 = xr @ W2  [N,64]@[64,32] ------------------------
// 128 threads, tile 256 rows x 32 cols, 8x8 per-thread register tile.
__global__ void gemm2_kernel(const float* __restrict__ W) {
    __shared__ float xs[256][17];
    __shared__ float ws[16][36];

    int tid = threadIdx.x;
    int tx  = tid & 3;              // col group: cols tx*8..+7
    int ty  = tid >> 2;             // row group: rows ty*8..+7 (0..31)
    int row0 = blockIdx.x * 256;

    float acc[8][8] = {};

    for (int k0 = 0; k0 < F_MID; k0 += 16) {
        #pragma unroll
        for (int p = 0; p < 8; p++) {
            int f  = p * 128 + tid;
            int r  = f >> 2;
            int kq = f & 3;
            int gr = min(row0 + r, N_NODES - 1);
            float4 v = *(const float4*)&g_xr[(size_t)gr * F_MID + k0 + kq * 4];
            xs[r][kq * 4 + 0] = v.x;
            xs[r][kq * 4 + 1] = v.y;
            xs[r][kq * 4 + 2] = v.z;
            xs[r][kq * 4 + 3] = v.w;
        }
        {
            int wk = tid >> 3, wc = tid & 7;   // 16x32 = 512 floats = 128 float4
            *(float4*)&ws[wk][wc * 4] = *(const float4*)&W[(k0 + wk) * F_OUT + wc * 4];
        }
        __syncthreads();

        #pragma unroll
        for (int k = 0; k < 16; k++) {
            float a[8], b[8];
            #pragma unroll
            for (int i = 0; i < 8; i++) a[i] = xs[ty * 8 + i][k];
            *(float4*)&b[0] = *(float4*)&ws[k][tx * 8];
            *(float4*)&b[4] = *(float4*)&ws[k][tx * 8 + 4];
            #pragma unroll
            for (int i = 0; i < 8; i++)
                #pragma unroll
                for (int j = 0; j < 8; j++)
                    acc[i][j] += a[i] * b[j];
        }
        __syncthreads();
    }

    #pragma unroll
    for (int i = 0; i < 8; i++) {
        int r = row0 + ty * 8 + i;
        if (r < N_NODES) {
            *(float4*)&g_h2[(size_t)r * F_OUT + tx * 8] =
                make_float4(acc[i][0], acc[i][1], acc[i][2], acc[i][3]);
            *(float4*)&g_h2[(size_t)r * F_OUT + tx * 8 + 4] =
                make_float4(acc[i][4], acc[i][5], acc[i][6], acc[i][7]);
        }
    }
}

// ---------------- pull layer 2: out = sum(h2[src])*in_norm + b2 -------------
// 8 threads per node, 32 nodes per 256-thread block.
__global__ void pull2_kernel(const float* __restrict__ b2,
                             float* __restrict__ out) {
    int t = threadIdx.x;
    int node = blockIdx.x * 32 + (t >> 3);
    int c = t & 7;
    if (node >= N_NODES) return;
    int beg = g_row_ptr[node];
    int deg = g_in_deg[node];
    float4 acc = make_float4(0.f, 0.f, 0.f, 0.f);
    int j = 0;
    for (; j + 4 <= deg; j += 4) {
        int s0 = __ldg(&g_csr_src[beg + j + 0]);
        int s1 = __ldg(&g_csr_src[beg + j + 1]);
        int s2 = __ldg(&g_csr_src[beg + j + 2]);
        int s3 = __ldg(&g_csr_src[beg + j + 3]);
        float4 v0 = *(const float4*)&g_h2[(size_t)s0 * F_OUT + c * 4];
        float4 v1 = *(const float4*)&g_h2[(size_t)s1 * F_OUT + c * 4];
        float4 v2 = *(const float4*)&g_h2[(size_t)s2 * F_OUT + c * 4];
        float4 v3 = *(const float4*)&g_h2[(size_t)s3 * F_OUT + c * 4];
        acc.x += (v0.x + v1.x) + (v2.x + v3.x);
        acc.y += (v0.y + v1.y) + (v2.y + v3.y);
        acc.z += (v0.z + v1.z) + (v2.z + v3.z);
        acc.w += (v0.w + v1.w) + (v2.w + v3.w);
    }
    for (; j < deg; j++) {
        int s = __ldg(&g_csr_src[beg + j]);
        float4 v = *(const float4*)&g_h2[(size_t)s * F_OUT + c * 4];
        acc.x += v.x; acc.y += v.y; acc.z += v.z; acc.w += v.w;
    }
    float ni = g_nrm_in[node];
    float4 bb = *(const float4*)&b2[c * 4];
    float4 r;
    r.x = fmaf(acc.x, ni, bb.x);
    r.y = fmaf(acc.y, ni, bb.y);
    r.z = fmaf(acc.z, ni, bb.z);
    r.w = fmaf(acc.w, ni, bb.w);
    *(float4*)&out[(size_t)node * F_OUT + c * 4] = r;
}

// ---------------- launch -----------------------------------------------------
extern "C" void kernel_launch(void* const* d_in, const int* in_sizes, int n_in,
                              void* d_out, int out_size) {
    const float* x   = (const float*)d_in[0];
    const int*   src = (const int*)  d_in[1];
    const int*   dst = (const int*)  d_in[2];
    const float* W1  = (const float*)d_in[3];
    const float* b1  = (const float*)d_in[4];
    const float* W2  = (const float*)d_in[5];
    const float* b2  = (const float*)d_in[6];
    int E = in_sizes[1];
    float* out = (float*)d_out;

    int nblk = (N_NODES + 511) / 512;   // 196

    zero_kernel  <<<(N_NODES + 255) / 256, 256>>>();
    degree_kernel<<<(E + 255) / 256, 256>>>(src, dst, E);
    norm_kernel  <<<(N_NODES + 255) / 256, 256>>>();
    scan1_kernel <<<nblk, 512>>>();
    scan2_kernel <<<1, 256>>>(nblk);
    scan3_kernel <<<nblk, 512>>>();
    fill_kernel  <<<(E + 255) / 256, 256>>>(src, dst, E);
    gemm1_kernel <<<(N_NODES + 127) / 128, 128>>>(x, W1);
    pull1_kernel <<<(N_NODES + 15) / 16, 256>>>(b1);
    gemm2_kernel <<<(N_NODES + 255) / 256, 128>>>(W2);
    pull2_kernel <<<(N_NODES + 31) / 32, 256>>>(b2, out);
}

// round 3
// speedup vs baseline: 1.5192x; 1.1035x over previous
#include <cuda_runtime.h>
#include <cuda_fp16.h>

#define N_NODES 100000
#define E_MAX   1600000
#define F_IN  128
#define F_MID 64
#define F_OUT 32

// ---------------- scratch (device globals; no allocations allowed) ----------
__device__ int    g_out_deg[N_NODES];
__device__ int    g_in_deg [N_NODES];
__device__ float  g_nrm_out[N_NODES];
__device__ float  g_nrm_in [N_NODES];
__device__ int    g_row_ptr[N_NODES];
__device__ int    g_wp     [N_NODES];       // write cursor for CSR fill
__device__ int    g_blk_sum[512];
__device__ int    g_blk_off[512];
__device__ int    g_csr_src[E_MAX];
__device__ __half g_h1[N_NODES * F_MID];    // fp16: out_norm*(x@W1)
__device__ float  g_xr[N_NODES * F_MID];    // fp32: relu(agg*in_norm+b1)*out_norm
__device__ __half g_h2[N_NODES * F_OUT];    // fp16: xr@W2

// ---------------- zero degree counters --------------------------------------
__global__ void zero_kernel() {
    int i = blockIdx.x * 256 + threadIdx.x;
    if (i < N_NODES) { g_out_deg[i] = 0; g_in_deg[i] = 0; }
}

// ---------------- degrees (int atomics), 4 edges/thread ----------------------
__global__ void degree_kernel(const int* __restrict__ src,
                              const int* __restrict__ dst, int E) {
    int i = blockIdx.x * 256 + threadIdx.x;
    int e0 = i * 4;
    if (e0 + 3 < E) {
        int4 s = *(const int4*)&src[e0];
        int4 d = *(const int4*)&dst[e0];
        atomicAdd(&g_out_deg[s.x], 1); atomicAdd(&g_in_deg[d.x], 1);
        atomicAdd(&g_out_deg[s.y], 1); atomicAdd(&g_in_deg[d.y], 1);
        atomicAdd(&g_out_deg[s.z], 1); atomicAdd(&g_in_deg[d.z], 1);
        atomicAdd(&g_out_deg[s.w], 1); atomicAdd(&g_in_deg[d.w], 1);
    } else {
        for (int e = e0; e < E; e++) {
            atomicAdd(&g_out_deg[src[e]], 1);
            atomicAdd(&g_in_deg [dst[e]], 1);
        }
    }
}

// ---------------- scan phase 1 (+ fused norm computation) --------------------
__global__ void scan1_kernel() {
    int tid = threadIdx.x;
    int i = blockIdx.x * 512 + tid;
    int v = (i < N_NODES) ? g_in_deg[i] : 0;
    int lane = tid & 31, w = tid >> 5;
    int x = v;
    #pragma unroll
    for (int o = 1; o < 32; o <<= 1) {
        int t = __shfl_up_sync(0xffffffffu, x, o);
        if (lane >= o) x += t;
    }
    __shared__ int wsum[16];
    if (lane == 31) wsum[w] = x;
    __syncthreads();
    if (w == 0) {
        int t = (lane < 16) ? wsum[lane] : 0;
        #pragma unroll
        for (int o = 1; o < 16; o <<= 1) {
            int u = __shfl_up_sync(0xffffffffu, t, o);
            if (lane >= o) t += u;
        }
        if (lane < 16) wsum[lane] = t;
    }
    __syncthreads();
    int base = (w > 0) ? wsum[w - 1] : 0;
    if (i < N_NODES) {
        g_row_ptr[i] = base + x - v;
        g_nrm_in [i] = rsqrtf((float)max(v, 1));
        g_nrm_out[i] = rsqrtf((float)max(g_out_deg[i], 1));
    }
    if (tid == 511) g_blk_sum[blockIdx.x] = wsum[15];
}

__global__ void scan2_kernel(int nblk) {
    int tid = threadIdx.x;           // 256 threads
    int v = (tid < nblk) ? g_blk_sum[tid] : 0;
    int lane = tid & 31, w = tid >> 5;
    int x = v;
    #pragma unroll
    for (int o = 1; o < 32; o <<= 1) {
        int t = __shfl_up_sync(0xffffffffu, x, o);
        if (lane >= o) x += t;
    }
    __shared__ int wsum[8];
    if (lane == 31) wsum[w] = x;
    __syncthreads();
    if (w == 0) {
        int t = (lane < 8) ? wsum[lane] : 0;
        #pragma unroll
        for (int o = 1; o < 8; o <<= 1) {
            int u = __shfl_up_sync(0xffffffffu, t, o);
            if (lane >= o) t += u;
        }
        if (lane < 8) wsum[lane] = t;
    }
    __syncthreads();
    int base = (w > 0) ? wsum[w - 1] : 0;
    if (tid < nblk) g_blk_off[tid] = base + x - v;
}

__global__ void scan3_kernel() {
    int i = blockIdx.x * 512 + threadIdx.x;
    if (i < N_NODES) {
        int r = g_row_ptr[i] + g_blk_off[blockIdx.x];
        g_row_ptr[i] = r;
        g_wp[i]      = r;
    }
}

// ---------------- CSR fill (atomic bump on write cursor) ---------------------
__global__ void fill_kernel(const int* __restrict__ src,
                            const int* __restrict__ dst, int E) {
    int e = blockIdx.x * 256 + threadIdx.x;
    if (e < E) {
        int pos = atomicAdd(&g_wp[dst[e]], 1);
        g_csr_src[pos] = src[e];
    }
}

// ---------------- GEMM1: h1(fp16) = out_norm * (x @ W1)  [N,128]@[128,64] ----
// 128 threads, tile 128 rows x 64 cols, 8x8 per-thread register tile.
__global__ void gemm1_kernel(const float* __restrict__ x,
                             const float* __restrict__ W) {
    __shared__ float xs[128][17];
    __shared__ float ws[16][68];

    int tid = threadIdx.x;
    int tx  = tid & 7;
    int ty  = tid >> 3;
    int row0 = blockIdx.x * 128;

    float acc[8][8] = {};

    for (int k0 = 0; k0 < F_IN; k0 += 16) {
        #pragma unroll
        for (int p = 0; p < 4; p++) {
            int f  = p * 128 + tid;
            int r  = f >> 2;
            int kq = f & 3;
            int gr = min(row0 + r, N_NODES - 1);
            float4 v = *(const float4*)&x[(size_t)gr * F_IN + k0 + kq * 4];
            xs[r][kq * 4 + 0] = v.x;
            xs[r][kq * 4 + 1] = v.y;
            xs[r][kq * 4 + 2] = v.z;
            xs[r][kq * 4 + 3] = v.w;
        }
        {
            int wk = tid >> 3, wc = tid & 7;
            *(float4*)&ws[wk][wc * 8]     = *(const float4*)&W[(k0 + wk) * F_MID + wc * 8];
            *(float4*)&ws[wk][wc * 8 + 4] = *(const float4*)&W[(k0 + wk) * F_MID + wc * 8 + 4];
        }
        __syncthreads();

        #pragma unroll
        for (int k = 0; k < 16; k++) {
            float a[8], b[8];
            #pragma unroll
            for (int i = 0; i < 8; i++) a[i] = xs[ty * 8 + i][k];
            *(float4*)&b[0] = *(float4*)&ws[k][tx * 8];
            *(float4*)&b[4] = *(float4*)&ws[k][tx * 8 + 4];
            #pragma unroll
            for (int i = 0; i < 8; i++)
                #pragma unroll
                for (int j = 0; j < 8; j++)
                    acc[i][j] += a[i] * b[j];
        }
        __syncthreads();
    }

    #pragma unroll
    for (int i = 0; i < 8; i++) {
        int r = row0 + ty * 8 + i;
        if (r < N_NODES) {
            float nm = g_nrm_out[r];
            __half2 o[4];
            #pragma unroll
            for (int q = 0; q < 4; q++)
                o[q] = __floats2half2_rn(acc[i][q*2] * nm, acc[i][q*2+1] * nm);
            *(float4*)&g_h1[(size_t)r * F_MID + tx * 8] = *(float4*)o;
        }
    }
}

// ---------------- pull layer 1: xr = relu(sum(h1[src])*in_norm + b1)*out_norm
// 8 threads/node (8 fp16 feats each = 16B load/edge), 32 nodes per block.
__global__ void pull1_kernel(const float* __restrict__ b1) {
    int t = threadIdx.x;
    int node = blockIdx.x * 32 + (t >> 3);
    int c = t & 7;                       // feature chunk: feats c*8..c*8+7
    if (node >= N_NODES) return;
    int beg = g_row_ptr[node];
    int deg = g_in_deg[node];
    float acc[8] = {};
    int j = 0;
    for (; j + 4 <= deg; j += 4) {
        int s0 = __ldg(&g_csr_src[beg + j + 0]);
        int s1 = __ldg(&g_csr_src[beg + j + 1]);
        int s2 = __ldg(&g_csr_src[beg + j + 2]);
        int s3 = __ldg(&g_csr_src[beg + j + 3]);
        uint4 r0 = *(const uint4*)&g_h1[(size_t)s0 * F_MID + c * 8];
        uint4 r1 = *(const uint4*)&g_h1[(size_t)s1 * F_MID + c * 8];
        uint4 r2 = *(const uint4*)&g_h1[(size_t)s2 * F_MID + c * 8];
        uint4 r3 = *(const uint4*)&g_h1[(size_t)s3 * F_MID + c * 8];
        const __half2* h0 = (const __half2*)&r0;
        const __half2* h1p = (const __half2*)&r1;
        const __half2* h2p = (const __half2*)&r2;
        const __half2* h3 = (const __half2*)&r3;
        #pragma unroll
        for (int q = 0; q < 4; q++) {
            float2 f0 = __half22float2(h0[q]);
            float2 f1 = __half22float2(h1p[q]);
            float2 f2 = __half22float2(h2p[q]);
            float2 f3 = __half22float2(h3[q]);
            acc[q*2]   += (f0.x + f1.x) + (f2.x + f3.x);
            acc[q*2+1] += (f0.y + f1.y) + (f2.y + f3.y);
        }
    }
    for (; j < deg; j++) {
        int s = __ldg(&g_csr_src[beg + j]);
        uint4 r0 = *(const uint4*)&g_h1[(size_t)s * F_MID + c * 8];
        const __half2* h0 = (const __half2*)&r0;
        #pragma unroll
        for (int q = 0; q < 4; q++) {
            float2 f0 = __half22float2(h0[q]);
            acc[q*2] += f0.x; acc[q*2+1] += f0.y;
        }
    }
    float ni = g_nrm_in[node];
    float no = g_nrm_out[node];
    float r[8];
    #pragma unroll
    for (int q = 0; q < 8; q++) {
        float bb = __ldg(&b1[c * 8 + q]);
        r[q] = fmaxf(fmaf(acc[q], ni, bb), 0.f) * no;
    }
    *(float4*)&g_xr[(size_t)node * F_MID + c * 8]     = *(float4*)&r[0];
    *(float4*)&g_xr[(size_t)node * F_MID + c * 8 + 4] = *(float4*)&r[4];
}

// ---------------- GEMM2: h2(fp16) = xr @ W2  [N,64]@[64,32] ------------------
__global__ void gemm2_kernel(const float* __restrict__ W) {
    __shared__ float xs[256][17];
    __shared__ float ws[16][36];

    int tid = threadIdx.x;
    int tx  = tid & 3;
    int ty  = tid >> 2;
    int row0 = blockIdx.x * 256;

    float acc[8][8] = {};

    for (int k0 = 0; k0 < F_MID; k0 += 16) {
        #pragma unroll
        for (int p = 0; p < 8; p++) {
            int f  = p * 128 + tid;
            int r  = f >> 2;
            int kq = f & 3;
            int gr = min(row0 + r, N_NODES - 1);
            float4 v = *(const float4*)&g_xr[(size_t)gr * F_MID + k0 + kq * 4];
            xs[r][kq * 4 + 0] = v.x;
            xs[r][kq * 4 + 1] = v.y;
            xs[r][kq * 4 + 2] = v.z;
            xs[r][kq * 4 + 3] = v.w;
        }
        {
            int wk = tid >> 3, wc = tid & 7;
            *(float4*)&ws[wk][wc * 4] = *(const float4*)&W[(k0 + wk) * F_OUT + wc * 4];
        }
        __syncthreads();

        #pragma unroll
        for (int k = 0; k < 16; k++) {
            float a[8], b[8];
            #pragma unroll
            for (int i = 0; i < 8; i++) a[i] = xs[ty * 8 + i][k];
            *(float4*)&b[0] = *(float4*)&ws[k][tx * 8];
            *(float4*)&b[4] = *(float4*)&ws[k][tx * 8 + 4];
            #pragma unroll
            for (int i = 0; i < 8; i++)
                #pragma unroll
                for (int j = 0; j < 8; j++)
                    acc[i][j] += a[i] * b[j];
        }
        __syncthreads();
    }

    #pragma unroll
    for (int i = 0; i < 8; i++) {
        int r = row0 + ty * 8 + i;
        if (r < N_NODES) {
            __half2 o[4];
            #pragma unroll
            for (int q = 0; q < 4; q++)
                o[q] = __floats2half2_rn(acc[i][q*2], acc[i][q*2+1]);
            *(float4*)&g_h2[(size_t)r * F_OUT + tx * 8] = *(float4*)o;
        }
    }
}

// ---------------- pull layer 2: out = sum(h2[src])*in_norm + b2 --------------
// 4 threads/node (8 fp16 feats each), 64 nodes per block.
__global__ void pull2_kernel(const float* __restrict__ b2,
                             float* __restrict__ out) {
    int t = threadIdx.x;
    int node = blockIdx.x * 64 + (t >> 2);
    int c = t & 3;                       // feats c*8..c*8+7
    if (node >= N_NODES) return;
    int beg = g_row_ptr[node];
    int deg = g_in_deg[node];
    float acc[8] = {};
    int j = 0;
    for (; j + 4 <= deg; j += 4) {
        int s0 = __ldg(&g_csr_src[beg + j + 0]);
        int s1 = __ldg(&g_csr_src[beg + j + 1]);
        int s2 = __ldg(&g_csr_src[beg + j + 2]);
        int s3 = __ldg(&g_csr_src[beg + j + 3]);
        uint4 r0 = *(const uint4*)&g_h2[(size_t)s0 * F_OUT + c * 8];
        uint4 r1 = *(const uint4*)&g_h2[(size_t)s1 * F_OUT + c * 8];
        uint4 r2 = *(const uint4*)&g_h2[(size_t)s2 * F_OUT + c * 8];
        uint4 r3 = *(const uint4*)&g_h2[(size_t)s3 * F_OUT + c * 8];
        const __half2* h0 = (const __half2*)&r0;
        const __half2* h1p = (const __half2*)&r1;
        const __half2* h2p = (const __half2*)&r2;
        const __half2* h3 = (const __half2*)&r3;
        #pragma unroll
        for (int q = 0; q < 4; q++) {
            float2 f0 = __half22float2(h0[q]);
            float2 f1 = __half22float2(h1p[q]);
            float2 f2 = __half22float2(h2p[q]);
            float2 f3 = __half22float2(h3[q]);
            acc[q*2]   += (f0.x + f1.x) + (f2.x + f3.x);
            acc[q*2+1] += (f0.y + f1.y) + (f2.y + f3.y);
        }
    }
    for (; j < deg; j++) {
        int s = __ldg(&g_csr_src[beg + j]);
        uint4 r0 = *(const uint4*)&g_h2[(size_t)s * F_OUT + c * 8];
        const __half2* h0 = (const __half2*)&r0;
        #pragma unroll
        for (int q = 0; q < 4; q++) {
            float2 f0 = __half22float2(h0[q]);
            acc[q*2] += f0.x; acc[q*2+1] += f0.y;
        }
    }
    float ni = g_nrm_in[node];
    float r[8];
    #pragma unroll
    for (int q = 0; q < 8; q++) {
        float bb = __ldg(&b2[c * 8 + q]);
        r[q] = fmaf(acc[q], ni, bb);
    }
    *(float4*)&out[(size_t)node * F_OUT + c * 8]     = *(float4*)&r[0];
    *(float4*)&out[(size_t)node * F_OUT + c * 8 + 4] = *(float4*)&r[4];
}

// ---------------- launch -----------------------------------------------------
extern "C" void kernel_launch(void* const* d_in, const int* in_sizes, int n_in,
                              void* d_out, int out_size) {
    const float* x   = (const float*)d_in[0];
    const int*   src = (const int*)  d_in[1];
    const int*   dst = (const int*)  d_in[2];
    const float* W1  = (const float*)d_in[3];
    const float* b1  = (const float*)d_in[4];
    const float* W2  = (const float*)d_in[5];
    const float* b2  = (const float*)d_in[6];
    int E = in_sizes[1];
    float* out = (float*)d_out;

    int nblk = (N_NODES + 511) / 512;   // 196

    zero_kernel  <<<(N_NODES + 255) / 256, 256>>>();
    degree_kernel<<<((E + 3) / 4 + 255) / 256, 256>>>(src, dst, E);
    scan1_kernel <<<nblk, 512>>>();
    scan2_kernel <<<1, 256>>>(nblk);
    scan3_kernel <<<nblk, 512>>>();
    fill_kernel  <<<(E + 255) / 256, 256>>>(src, dst, E);
    gemm1_kernel <<<(N_NODES + 127) / 128, 128>>>(x, W1);
    pull1_kernel <<<(N_NODES + 31) / 32, 256>>>(b1);
    gemm2_kernel <<<(N_NODES + 255) / 256, 128>>>(W2);
    pull2_kernel <<<(N_NODES + 63) / 64, 256>>>(b2, out);
}

// round 4
// speedup vs baseline: 1.8505x; 1.2181x over previous
#include <cuda_runtime.h>
#include <cuda_fp16.h>
#include <mma.h>
using namespace nvcuda;

#define N_NODES 100000
#define E_MAX   1600000
#define F_IN  128
#define F_MID 64
#define F_OUT 32

// ---------------- scratch ----------------------------------------------------
__device__ int    g_out_deg[N_NODES];
__device__ int    g_in_deg [N_NODES];
__device__ float  g_nrm_out[N_NODES];
__device__ float  g_nrm_in [N_NODES];
__device__ int    g_row_ptr[N_NODES];
__device__ int    g_wp     [N_NODES];
__device__ int    g_blk_sum[512];
__device__ int    g_csr_src[E_MAX];
__device__ __half g_h1[N_NODES * F_MID];    // out_norm*(x@W1), fp16
__device__ __half g_xr[N_NODES * F_MID];    // relu(agg*in_norm+b1)*out_norm, fp16
__device__ __half g_h2[N_NODES * F_OUT];    // xr@W2, fp16

// ---------------- zero degree counters --------------------------------------
__global__ void zero_kernel() {
    int i = blockIdx.x * 256 + threadIdx.x;
    if (i < N_NODES) { g_out_deg[i] = 0; g_in_deg[i] = 0; }
}

// ---------------- degrees, 4 edges/thread ------------------------------------
__global__ void degree_kernel(const int* __restrict__ src,
                              const int* __restrict__ dst, int E) {
    int i = blockIdx.x * 256 + threadIdx.x;
    int e0 = i * 4;
    if (e0 + 3 < E) {
        int4 s = *(const int4*)&src[e0];
        int4 d = *(const int4*)&dst[e0];
        atomicAdd(&g_out_deg[s.x], 1); atomicAdd(&g_in_deg[d.x], 1);
        atomicAdd(&g_out_deg[s.y], 1); atomicAdd(&g_in_deg[d.y], 1);
        atomicAdd(&g_out_deg[s.z], 1); atomicAdd(&g_in_deg[d.z], 1);
        atomicAdd(&g_out_deg[s.w], 1); atomicAdd(&g_in_deg[d.w], 1);
    } else {
        for (int e = e0; e < E; e++) {
            atomicAdd(&g_out_deg[src[e]], 1);
            atomicAdd(&g_in_deg [dst[e]], 1);
        }
    }
}

// ---------------- scan phase 1 (+ fused norms) -------------------------------
__global__ void scan1_kernel() {
    int tid = threadIdx.x;
    int i = blockIdx.x * 512 + tid;
    int v = (i < N_NODES) ? g_in_deg[i] : 0;
    int lane = tid & 31, w = tid >> 5;
    int x = v;
    #pragma unroll
    for (int o = 1; o < 32; o <<= 1) {
        int t = __shfl_up_sync(0xffffffffu, x, o);
        if (lane >= o) x += t;
    }
    __shared__ int wsum[16];
    if (lane == 31) wsum[w] = x;
    __syncthreads();
    if (w == 0) {
        int t = (lane < 16) ? wsum[lane] : 0;
        #pragma unroll
        for (int o = 1; o < 16; o <<= 1) {
            int u = __shfl_up_sync(0xffffffffu, t, o);
            if (lane >= o) t += u;
        }
        if (lane < 16) wsum[lane] = t;
    }
    __syncthreads();
    int base = (w > 0) ? wsum[w - 1] : 0;
    if (i < N_NODES) {
        g_row_ptr[i] = base + x - v;
        g_nrm_in [i] = rsqrtf((float)max(v, 1));
        g_nrm_out[i] = rsqrtf((float)max(g_out_deg[i], 1));
    }
    if (tid == 511) g_blk_sum[blockIdx.x] = wsum[15];
}

// ---------------- scan phase 2+3 fused: add block offset, init write cursor --
__global__ void scan3_kernel() {
    __shared__ int s_off;
    int tid = threadIdx.x;
    if (tid < 32) {
        int acc = 0;
        for (int b = tid; b < (int)blockIdx.x; b += 32) acc += g_blk_sum[b];
        #pragma unroll
        for (int o = 16; o > 0; o >>= 1)
            acc += __shfl_down_sync(0xffffffffu, acc, o);
        if (tid == 0) s_off = acc;
    }
    __syncthreads();
    int i = blockIdx.x * 512 + tid;
    if (i < N_NODES) {
        int r = g_row_ptr[i] + s_off;
        g_row_ptr[i] = r;
        g_wp[i]      = r;
    }
}

// ---------------- CSR fill ----------------------------------------------------
__global__ void fill_kernel(const int* __restrict__ src,
                            const int* __restrict__ dst, int E) {
    int e = blockIdx.x * 256 + threadIdx.x;
    if (e < E) {
        int pos = atomicAdd(&g_wp[dst[e]], 1);
        g_csr_src[pos] = src[e];
    }
}

// ---------------- GEMM1 (wmma): h1 = out_norm * (x @ W1)  [N,128]@[128,64] ---
// 256 threads (8 warps), tile 128 rows x 64 cols, K chunks of 64.
__global__ void gemm1_kernel(const float* __restrict__ x,
                             const float* __restrict__ W) {
    __shared__ __align__(16) unsigned char sraw[34816];
    __half (*xs)[72] = (__half(*)[72])sraw;                 // 128 x 64 (pad 72)
    __half (*ws)[72] = (__half(*)[72])(sraw + 18432);       // 64  x 64 (pad 72)
    float  (*cs)[68] = (float (*)[68])sraw;                 // epilogue reuse 128x64

    int tid  = threadIdx.x;
    int warp = tid >> 5;
    int row0 = blockIdx.x * 128;

    wmma::fragment<wmma::accumulator, 16, 16, 16, float> cf[4];
    #pragma unroll
    for (int j = 0; j < 4; j++) wmma::fill_fragment(cf[j], 0.0f);

    #pragma unroll
    for (int c = 0; c < 2; c++) {
        int kc = c * 64;
        // x chunk: 128 rows x 64 K -> fp16 smem (2048 float4, 8/thread)
        #pragma unroll
        for (int p = 0; p < 8; p++) {
            int f  = p * 256 + tid;
            int r  = f >> 4;
            int kq = f & 15;
            int gr = min(row0 + r, N_NODES - 1);
            float4 v = *(const float4*)&x[(size_t)gr * F_IN + kc + kq * 4];
            __half2 h0 = __floats2half2_rn(v.x, v.y);
            __half2 h1 = __floats2half2_rn(v.z, v.w);
            *(__half2*)&xs[r][kq * 4]     = h0;
            *(__half2*)&xs[r][kq * 4 + 2] = h1;
        }
        // W chunk: 64 rows x 64 cols (1024 float4, 4/thread)
        #pragma unroll
        for (int p = 0; p < 4; p++) {
            int f  = p * 256 + tid;
            int r  = f >> 4;
            int cq = f & 15;
            float4 v = *(const float4*)&W[(size_t)(kc + r) * F_MID + cq * 4];
            *(__half2*)&ws[r][cq * 4]     = __floats2half2_rn(v.x, v.y);
            *(__half2*)&ws[r][cq * 4 + 2] = __floats2half2_rn(v.z, v.w);
        }
        __syncthreads();

        #pragma unroll
        for (int k = 0; k < 4; k++) {
            wmma::fragment<wmma::matrix_a, 16, 16, 16, __half, wmma::row_major> af;
            wmma::load_matrix_sync(af, &xs[warp * 16][k * 16], 72);
            #pragma unroll
            for (int j = 0; j < 4; j++) {
                wmma::fragment<wmma::matrix_b, 16, 16, 16, __half, wmma::row_major> bf;
                wmma::load_matrix_sync(bf, &ws[k * 16][j * 16], 72);
                wmma::mma_sync(cf[j], af, bf, cf[j]);
            }
        }
        __syncthreads();
    }

    // epilogue: frags -> float smem -> scale -> fp16 global
    #pragma unroll
    for (int j = 0; j < 4; j++)
        wmma::store_matrix_sync(&cs[warp * 16][j * 16], cf[j], 68, wmma::mem_row_major);
    __syncthreads();

    #pragma unroll
    for (int p = 0; p < 4; p++) {
        int f  = p * 256 + tid;       // 1024 uint4: 128 rows x 8
        int r  = f >> 3;
        int c8 = f & 7;
        int gr = row0 + r;
        if (gr < N_NODES) {
            float nm = g_nrm_out[gr];
            const float* row = cs[r];
            __half2 o[4];
            #pragma unroll
            for (int q = 0; q < 4; q++)
                o[q] = __floats2half2_rn(row[c8 * 8 + q * 2] * nm,
                                         row[c8 * 8 + q * 2 + 1] * nm);
            *(uint4*)&g_h1[(size_t)gr * F_MID + c8 * 8] = *(uint4*)o;
        }
    }
}

// ---------------- pull layer 1 -> xr (fp16) ----------------------------------
// 8 threads/node, 32 nodes/block.
__global__ void pull1_kernel(const float* __restrict__ b1) {
    int t = threadIdx.x;
    int node = blockIdx.x * 32 + (t >> 3);
    int c = t & 7;
    if (node >= N_NODES) return;
    int beg = g_row_ptr[node];
    int deg = g_in_deg[node];
    float acc[8] = {};
    int j = 0;
    for (; j + 4 <= deg; j += 4) {
        int s0 = __ldg(&g_csr_src[beg + j + 0]);
        int s1 = __ldg(&g_csr_src[beg + j + 1]);
        int s2 = __ldg(&g_csr_src[beg + j + 2]);
        int s3 = __ldg(&g_csr_src[beg + j + 3]);
        uint4 r0 = *(const uint4*)&g_h1[(size_t)s0 * F_MID + c * 8];
        uint4 r1 = *(const uint4*)&g_h1[(size_t)s1 * F_MID + c * 8];
        uint4 r2 = *(const uint4*)&g_h1[(size_t)s2 * F_MID + c * 8];
        uint4 r3 = *(const uint4*)&g_h1[(size_t)s3 * F_MID + c * 8];
        const __half2* h0 = (const __half2*)&r0;
        const __half2* h1p = (const __half2*)&r1;
        const __half2* h2p = (const __half2*)&r2;
        const __half2* h3 = (const __half2*)&r3;
        #pragma unroll
        for (int q = 0; q < 4; q++) {
            float2 f0 = __half22float2(h0[q]);
            float2 f1 = __half22float2(h1p[q]);
            float2 f2 = __half22float2(h2p[q]);
            float2 f3 = __half22float2(h3[q]);
            acc[q*2]   += (f0.x + f1.x) + (f2.x + f3.x);
            acc[q*2+1] += (f0.y + f1.y) + (f2.y + f3.y);
        }
    }
    for (; j < deg; j++) {
        int s = __ldg(&g_csr_src[beg + j]);
        uint4 r0 = *(const uint4*)&g_h1[(size_t)s * F_MID + c * 8];
        const __half2* h0 = (const __half2*)&r0;
        #pragma unroll
        for (int q = 0; q < 4; q++) {
            float2 f0 = __half22float2(h0[q]);
            acc[q*2] += f0.x; acc[q*2+1] += f0.y;
        }
    }
    float ni = g_nrm_in[node];
    float no = g_nrm_out[node];
    __half2 o[4];
    #pragma unroll
    for (int q = 0; q < 4; q++) {
        float b0 = __ldg(&b1[c * 8 + q * 2]);
        float b1v = __ldg(&b1[c * 8 + q * 2 + 1]);
        float r0 = fmaxf(fmaf(acc[q*2],   ni, b0),  0.f) * no;
        float r1 = fmaxf(fmaf(acc[q*2+1], ni, b1v), 0.f) * no;
        o[q] = __floats2half2_rn(r0, r1);
    }
    *(uint4*)&g_xr[(size_t)node * F_MID + c * 8] = *(uint4*)o;
}

// ---------------- GEMM2 (wmma): h2 = xr @ W2  [N,64]@[64,32] -----------------
// 256 threads (8 warps), tile 128 rows x 32 cols, K=64 single chunk.
__global__ void gemm2_kernel(const float* __restrict__ W) {
    __shared__ __align__(16) unsigned char sraw[23552];
    __half (*xs)[72] = (__half(*)[72])sraw;                 // 128 x 64
    __half (*ws)[40] = (__half(*)[40])(sraw + 18432);       // 64 x 32
    float  (*cs)[36] = (float (*)[36])sraw;                 // 128 x 32 reuse

    int tid  = threadIdx.x;
    int warp = tid >> 5;
    int row0 = blockIdx.x * 128;

    // xr tile: already fp16, straight copy (1024 uint4, 4/thread)
    #pragma unroll
    for (int p = 0; p < 4; p++) {
        int f  = p * 256 + tid;
        int r  = f >> 3;
        int c8 = f & 7;
        int gr = min(row0 + r, N_NODES - 1);
        uint4 v = *(const uint4*)&g_xr[(size_t)gr * F_MID + c8 * 8];
        *(uint4*)&xs[r][c8 * 8] = v;
    }
    // W2: 64x32 fp32 -> fp16 (512 float4, 2/thread)
    #pragma unroll
    for (int p = 0; p < 2; p++) {
        int f  = p * 256 + tid;
        int r  = f >> 3;
        int cq = f & 7;
        float4 v = *(const float4*)&W[(size_t)r * F_OUT + cq * 4];
        *(__half2*)&ws[r][cq * 4]     = __floats2half2_rn(v.x, v.y);
        *(__half2*)&ws[r][cq * 4 + 2] = __floats2half2_rn(v.z, v.w);
    }
    __syncthreads();

    wmma::fragment<wmma::accumulator, 16, 16, 16, float> cf[2];
    #pragma unroll
    for (int j = 0; j < 2; j++) wmma::fill_fragment(cf[j], 0.0f);

    #pragma unroll
    for (int k = 0; k < 4; k++) {
        wmma::fragment<wmma::matrix_a, 16, 16, 16, __half, wmma::row_major> af;
        wmma::load_matrix_sync(af, &xs[warp * 16][k * 16], 72);
        #pragma unroll
        for (int j = 0; j < 2; j++) {
            wmma::fragment<wmma::matrix_b, 16, 16, 16, __half, wmma::row_major> bf;
            wmma::load_matrix_sync(bf, &ws[k * 16][j * 16], 40);
            wmma::mma_sync(cf[j], af, bf, cf[j]);
        }
    }
    __syncthreads();

    #pragma unroll
    for (int j = 0; j < 2; j++)
        wmma::store_matrix_sync(&cs[warp * 16][j * 16], cf[j], 36, wmma::mem_row_major);
    __syncthreads();

    #pragma unroll
    for (int p = 0; p < 2; p++) {
        int f  = p * 256 + tid;       // 512 uint4: 128 rows x 4
        int r  = f >> 2;
        int c8 = f & 3;
        int gr = row0 + r;
        if (gr < N_NODES) {
            const float* row = cs[r];
            __half2 o[4];
            #pragma unroll
            for (int q = 0; q < 4; q++)
                o[q] = __floats2half2_rn(row[c8 * 8 + q * 2], row[c8 * 8 + q * 2 + 1]);
            *(uint4*)&g_h2[(size_t)gr * F_OUT + c8 * 8] = *(uint4*)o;
        }
    }
}

// ---------------- pull layer 2: out = sum(h2[src])*in_norm + b2 --------------
// 4 threads/node, 64 nodes/block.
__global__ void pull2_kernel(const float* __restrict__ b2,
                             float* __restrict__ out) {
    int t = threadIdx.x;
    int node = blockIdx.x * 64 + (t >> 2);
    int c = t & 3;
    if (node >= N_NODES) return;
    int beg = g_row_ptr[node];
    int deg = g_in_deg[node];
    float acc[8] = {};
    int j = 0;
    for (; j + 4 <= deg; j += 4) {
        int s0 = __ldg(&g_csr_src[beg + j + 0]);
        int s1 = __ldg(&g_csr_src[beg + j + 1]);
        int s2 = __ldg(&g_csr_src[beg + j + 2]);
        int s3 = __ldg(&g_csr_src[beg + j + 3]);
        uint4 r0 = *(const uint4*)&g_h2[(size_t)s0 * F_OUT + c * 8];
        uint4 r1 = *(const uint4*)&g_h2[(size_t)s1 * F_OUT + c * 8];
        uint4 r2 = *(const uint4*)&g_h2[(size_t)s2 * F_OUT + c * 8];
        uint4 r3 = *(const uint4*)&g_h2[(size_t)s3 * F_OUT + c * 8];
        const __half2* h0 = (const __half2*)&r0;
        const __half2* h1p = (const __half2*)&r1;
        const __half2* h2p = (const __half2*)&r2;
        const __half2* h3 = (const __half2*)&r3;
        #pragma unroll
        for (int q = 0; q < 4; q++) {
            float2 f0 = __half22float2(h0[q]);
            float2 f1 = __half22float2(h1p[q]);
            float2 f2 = __half22float2(h2p[q]);
            float2 f3 = __half22float2(h3[q]);
            acc[q*2]   += (f0.x + f1.x) + (f2.x + f3.x);
            acc[q*2+1] += (f0.y + f1.y) + (f2.y + f3.y);
        }
    }
    for (; j < deg; j++) {
        int s = __ldg(&g_csr_src[beg + j]);
        uint4 r0 = *(const uint4*)&g_h2[(size_t)s * F_OUT + c * 8];
        const __half2* h0 = (const __half2*)&r0;
        #pragma unroll
        for (int q = 0; q < 4; q++) {
            float2 f0 = __half22float2(h0[q]);
            acc[q*2] += f0.x; acc[q*2+1] += f0.y;
        }
    }
    float ni = g_nrm_in[node];
    float r[8];
    #pragma unroll
    for (int q = 0; q < 8; q++) {
        float bb = __ldg(&b2[c * 8 + q]);
        r[q] = fmaf(acc[q], ni, bb);
    }
    *(float4*)&out[(size_t)node * F_OUT + c * 8]     = *(float4*)&r[0];
    *(float4*)&out[(size_t)node * F_OUT + c * 8 + 4] = *(float4*)&r[4];
}

// ---------------- launch ------------------------------------------------------
extern "C" void kernel_launch(void* const* d_in, const int* in_sizes, int n_in,
                              void* d_out, int out_size) {
    const float* x   = (const float*)d_in[0];
    const int*   src = (const int*)  d_in[1];
    const int*   dst = (const int*)  d_in[2];
    const float* W1  = (const float*)d_in[3];
    const float* b1  = (const float*)d_in[4];
    const float* W2  = (const float*)d_in[5];
    const float* b2  = (const float*)d_in[6];
    int E = in_sizes[1];
    float* out = (float*)d_out;

    int nblk = (N_NODES + 511) / 512;   // 196

    zero_kernel  <<<(N_NODES + 255) / 256, 256>>>();
    degree_kernel<<<((E + 3) / 4 + 255) / 256, 256>>>(src, dst, E);
    scan1_kernel <<<nblk, 512>>>();
    scan3_kernel <<<nblk, 512>>>();
    fill_kernel  <<<(E + 255) / 256, 256>>>(src, dst, E);
    gemm1_kernel <<<(N_NODES + 127) / 128, 256>>>(x, W1);
    pull1_kernel <<<(N_NODES + 31) / 32, 256>>>(b1);
    gemm2_kernel <<<(N_NODES + 127) / 128, 256>>>(W2);
    pull2_kernel <<<(N_NODES + 63) / 64, 256>>>(b2, out);
}